// round 1
// baseline (speedup 1.0000x reference)
#include <cuda_runtime.h>
#include <cstddef>

#define N_NODES 100000
#define N_EDGES 1600000
#define IN_C  128
#define HID_C 128
#define OUT_C 64

// ---------------- scratch (module-static; no allocations) ----------------
__device__ float g_deg [N_NODES];
__device__ float g_dinv[N_NODES];
__device__ float g_h1  [(size_t)N_NODES * HID_C];   // x @ W1
__device__ float g_agg1[(size_t)N_NODES * HID_C];   // scatter sum, then relu'd in place
__device__ float g_h2  [(size_t)N_NODES * OUT_C];   // h1r @ W2

// vector reduction (sm_90+): 4 floats per L2 RMW instead of 1
__device__ __forceinline__ void red_add_v4(float* addr, float4 v) {
    asm volatile("red.global.add.v4.f32 [%0], {%1,%2,%3,%4};"
                 :: "l"(addr), "f"(v.x), "f"(v.y), "f"(v.z), "f"(v.w)
                 : "memory");
}

// ---------------- init: deg=1 (self loop), zero accumulators ----------------
__global__ void k_init(float* __restrict__ out) {
    int i = blockIdx.x * blockDim.x + threadIdx.x;
    int stride = gridDim.x * blockDim.x;
    for (int j = i; j < N_NODES; j += stride) g_deg[j] = 1.0f;

    float4 z = make_float4(0.f, 0.f, 0.f, 0.f);
    float4* a1 = (float4*)g_agg1;
    const int n1 = N_NODES * (HID_C / 4);
    for (int j = i; j < n1; j += stride) a1[j] = z;

    float4* o = (float4*)out;
    const int n2 = N_NODES * (OUT_C / 4);
    for (int j = i; j < n2; j += stride) o[j] = z;
}

// ---------------- degree of dst (incoming, self-loop pre-counted) ----------------
__global__ void k_deg(const int* __restrict__ dst) {
    int i = blockIdx.x * blockDim.x + threadIdx.x;
    if (i < N_EDGES) atomicAdd(&g_deg[dst[i]], 1.0f);
}

__global__ void k_dinv() {
    int i = blockIdx.x * blockDim.x + threadIdx.x;
    if (i < N_NODES) g_dinv[i] = rsqrtf(g_deg[i]);
}

// ---------------- fp32 tiled GEMM: C[M,NC] = A[M,128] @ W[128,NC] ----------------
template<int NC>
__global__ void __launch_bounds__(256) k_gemm(const float* __restrict__ A,
                                              const float* __restrict__ W,
                                              float* __restrict__ C, int M) {
    constexpr int TX   = NC / 8;     // threads along cols (16 or 8)
    constexpr int TY   = 256 / TX;   // threads along rows (16 or 32)
    constexpr int BM   = TY * 4;     // rows per block (64 or 128)
    constexpr int BK   = 32;
    constexpr int KTOT = 128;

    __shared__ float Xs[BK][BM + 4]; // transposed A tile (padded, 16B-aligned rows)
    __shared__ float Ws[BK][NC];

    const int tid  = threadIdx.x;
    const int tx   = tid % TX;
    const int ty   = tid / TX;
    const int row0 = blockIdx.x * BM;

    float acc[4][8];
#pragma unroll
    for (int i = 0; i < 4; i++)
#pragma unroll
        for (int j = 0; j < 8; j++) acc[i][j] = 0.f;

    for (int kc = 0; kc < KTOT; kc += BK) {
        // A tile, transposed into Xs[k][r]; BM*8 float4 slots / 256 threads
#pragma unroll
        for (int l = 0; l < BM / 32; l++) {
            int s = tid + l * 256;
            int r = s >> 3;
            int c = s & 7;
            float4 v = make_float4(0.f, 0.f, 0.f, 0.f);
            int row = row0 + r;
            if (row < M)
                v = *(const float4*)(A + (size_t)row * KTOT + kc + c * 4);
            Xs[c * 4 + 0][r] = v.x;
            Xs[c * 4 + 1][r] = v.y;
            Xs[c * 4 + 2][r] = v.z;
            Xs[c * 4 + 3][r] = v.w;
        }
        // W tile: BK x NC
#pragma unroll
        for (int l = 0; l < (BK * NC) / 1024; l++) {
            int s = tid + l * 256;
            int k = s / (NC / 4);
            int c = s % (NC / 4);
            *(float4*)&Ws[k][c * 4] =
                *(const float4*)(W + (size_t)(kc + k) * NC + c * 4);
        }
        __syncthreads();

#pragma unroll
        for (int k = 0; k < BK; k++) {
            float4 xv = *(const float4*)&Xs[k][ty * 4];
            float4 w0 = *(const float4*)&Ws[k][tx * 8];
            float4 w1 = *(const float4*)&Ws[k][tx * 8 + 4];
            float xr[4] = {xv.x, xv.y, xv.z, xv.w};
            float wr[8] = {w0.x, w0.y, w0.z, w0.w, w1.x, w1.y, w1.z, w1.w};
#pragma unroll
            for (int i = 0; i < 4; i++)
#pragma unroll
                for (int j = 0; j < 8; j++)
                    acc[i][j] += xr[i] * wr[j];
        }
        __syncthreads();
    }

#pragma unroll
    for (int i = 0; i < 4; i++) {
        int row = row0 + ty * 4 + i;
        if (row < M) {
            float* cp = C + (size_t)row * NC + tx * 8;
            *(float4*)cp       = make_float4(acc[i][0], acc[i][1], acc[i][2], acc[i][3]);
            *(float4*)(cp + 4) = make_float4(acc[i][4], acc[i][5], acc[i][6], acc[i][7]);
        }
    }
}

// ---------------- layer-1 scatter: one warp per edge (128 ch = 32 x float4) ----------------
__global__ void k_scatter1(const int* __restrict__ src, const int* __restrict__ dst) {
    int t = blockIdx.x * blockDim.x + threadIdx.x;
    int e = t >> 5;
    int lane = t & 31;
    if (e >= N_EDGES) return;
    int s = src[e];
    int d = dst[e];
    float nrm = g_dinv[s] * g_dinv[d];
    float4 v = ((const float4*)(g_h1 + (size_t)s * HID_C))[lane];
    v.x *= nrm; v.y *= nrm; v.z *= nrm; v.w *= nrm;
    red_add_v4(g_agg1 + (size_t)d * HID_C + lane * 4, v);
}

// ---------------- epilogue 1: agg1 = relu(agg1 + h1*dinv^2 + b1) ----------------
__global__ void k_post1(const float* __restrict__ b1) {
    int idx = blockIdx.x * blockDim.x + threadIdx.x;   // over N*32 float4
    if (idx >= N_NODES * (HID_C / 4)) return;
    int node = idx >> 5;
    int c4   = idx & 31;
    float di = g_dinv[node];
    float sl = di * di;
    float4 a  = ((float4*)g_agg1)[idx];
    float4 h  = ((const float4*)g_h1)[idx];
    float4 bb = ((const float4*)b1)[c4];
    a.x = fmaxf(fmaf(h.x, sl, a.x) + bb.x, 0.f);
    a.y = fmaxf(fmaf(h.y, sl, a.y) + bb.y, 0.f);
    a.z = fmaxf(fmaf(h.z, sl, a.z) + bb.z, 0.f);
    a.w = fmaxf(fmaf(h.w, sl, a.w) + bb.w, 0.f);
    ((float4*)g_agg1)[idx] = a;
}

// ---------------- layer-2 scatter: half warp per edge (64 ch = 16 x float4) ----------------
__global__ void k_scatter2(const int* __restrict__ src, const int* __restrict__ dst,
                           float* __restrict__ out) {
    int t = blockIdx.x * blockDim.x + threadIdx.x;
    int e = t >> 4;
    int lane = t & 15;
    if (e >= N_EDGES) return;
    int s = src[e];
    int d = dst[e];
    float nrm = g_dinv[s] * g_dinv[d];
    float4 v = ((const float4*)(g_h2 + (size_t)s * OUT_C))[lane];
    v.x *= nrm; v.y *= nrm; v.z *= nrm; v.w *= nrm;
    red_add_v4(out + (size_t)d * OUT_C + lane * 4, v);
}

// ---------------- epilogue 2: out += h2*dinv^2 + b2 ----------------
__global__ void k_post2(const float* __restrict__ b2, float* __restrict__ out) {
    int idx = blockIdx.x * blockDim.x + threadIdx.x;   // over N*16 float4
    if (idx >= N_NODES * (OUT_C / 4)) return;
    int node = idx >> 4;
    int c4   = idx & 15;
    float di = g_dinv[node];
    float sl = di * di;
    float4 o  = ((float4*)out)[idx];
    float4 h  = ((const float4*)g_h2)[idx];
    float4 bb = ((const float4*)b2)[c4];
    o.x = fmaf(h.x, sl, o.x) + bb.x;
    o.y = fmaf(h.y, sl, o.y) + bb.y;
    o.z = fmaf(h.z, sl, o.z) + bb.z;
    o.w = fmaf(h.w, sl, o.w) + bb.w;
    ((float4*)out)[idx] = o;
}

// ---------------- launch ----------------
extern "C" void kernel_launch(void* const* d_in, const int* in_sizes, int n_in,
                              void* d_out, int out_size) {
    const float* x  = (const float*)d_in[0];
    const int*   ei = (const int*)  d_in[1];
    const float* W1 = (const float*)d_in[2];
    const float* b1 = (const float*)d_in[3];
    const float* W2 = (const float*)d_in[4];
    const float* b2 = (const float*)d_in[5];
    const int* src = ei;
    const int* dst = ei + N_EDGES;
    float* out = (float*)d_out;

    float *h1p, *agg1p, *h2p;
    cudaGetSymbolAddress((void**)&h1p,  g_h1);
    cudaGetSymbolAddress((void**)&agg1p, g_agg1);
    cudaGetSymbolAddress((void**)&h2p,  g_h2);

    k_init<<<4096, 256>>>(out);
    k_deg<<<(N_EDGES + 255) / 256, 256>>>(dst);
    k_dinv<<<(N_NODES + 255) / 256, 256>>>();

    // layer 1
    k_gemm<HID_C><<<(N_NODES + 63) / 64, 256>>>(x, W1, h1p, N_NODES);
    k_scatter1<<<(N_EDGES * 32) / 256, 256>>>(src, dst);
    k_post1<<<(N_NODES * (HID_C / 4) + 255) / 256, 256>>>(b1);

    // layer 2
    k_gemm<OUT_C><<<(N_NODES + 127) / 128, 256>>>(agg1p, W2, h2p, N_NODES);
    k_scatter2<<<(N_EDGES * 16) / 256, 256>>>(src, dst, out);
    k_post2<<<(N_NODES * (OUT_C / 4) + 255) / 256, 256>>>(b2, out);
}

// round 6
// speedup vs baseline: 2.0133x; 2.0133x over previous
#include <cuda_runtime.h>
#include <cstddef>

#define N_NODES 100000
#define N_EDGES 1600000
#define IN_C  128
#define HID_C 128
#define OUT_C 64

#define SCAN_B 512
#define N_SCAN_BLKS ((N_NODES + SCAN_B - 1) / SCAN_B)   // 196

// ---------------- scratch (module-static; no allocations) ----------------
__device__ int   g_cnt   [N_NODES];
__device__ int   g_row   [N_NODES + 1];
__device__ int   g_cursor[N_NODES];
__device__ int   g_bsum  [N_SCAN_BLKS];
__device__ int   g_boff  [N_SCAN_BLKS];
__device__ int   g_srcs  [N_EDGES];                     // src ids sorted by dst
__device__ float g_dinv  [N_NODES];
__device__ float g_h1s   [(size_t)N_NODES * HID_C];     // dinv[n] * (x @ W1)[n]
__device__ float g_agg1r [(size_t)N_NODES * HID_C];     // relu'd layer-1 output
__device__ float g_h2s   [(size_t)N_NODES * OUT_C];     // dinv[n] * (agg1r @ W2)[n]

// ---------------- CSR build ----------------
__global__ void k_zero_cnt() {
    int i = blockIdx.x * blockDim.x + threadIdx.x;
    if (i < N_NODES) g_cnt[i] = 0;
}

__global__ void k_hist(const int* __restrict__ dst) {
    int i = blockIdx.x * blockDim.x + threadIdx.x;
    if (i < N_EDGES) atomicAdd(&g_cnt[dst[i]], 1);
}

// per-block inclusive scan of 512 counts; also computes dinv = rsqrt(cnt+1)
__global__ void k_scan1() {
    __shared__ int sh[SCAN_B];
    int i = blockIdx.x * SCAN_B + threadIdx.x;
    int v = (i < N_NODES) ? g_cnt[i] : 0;
    if (i < N_NODES) g_dinv[i] = rsqrtf((float)(v + 1));   // +1 self loop
    sh[threadIdx.x] = v;
    __syncthreads();
#pragma unroll
    for (int off = 1; off < SCAN_B; off <<= 1) {
        int t = (threadIdx.x >= off) ? sh[threadIdx.x - off] : 0;
        __syncthreads();
        sh[threadIdx.x] += t;
        __syncthreads();
    }
    if (i < N_NODES) g_row[i] = sh[threadIdx.x] - v;       // exclusive within block
    if (threadIdx.x == SCAN_B - 1) g_bsum[blockIdx.x] = sh[SCAN_B - 1];
}

// scan of block sums (single block)
__global__ void k_scan2() {
    __shared__ int sh[256];
    int v = (threadIdx.x < N_SCAN_BLKS) ? g_bsum[threadIdx.x] : 0;
    sh[threadIdx.x] = v;
    __syncthreads();
#pragma unroll
    for (int off = 1; off < 256; off <<= 1) {
        int t = (threadIdx.x >= off) ? sh[threadIdx.x - off] : 0;
        __syncthreads();
        sh[threadIdx.x] += t;
        __syncthreads();
    }
    if (threadIdx.x < N_SCAN_BLKS) g_boff[threadIdx.x] = sh[threadIdx.x] - v;
    if (threadIdx.x == 0) g_row[N_NODES] = N_EDGES;
}

__global__ void k_scan3() {
    int i = blockIdx.x * blockDim.x + threadIdx.x;
    if (i < N_NODES) {
        int r = g_row[i] + g_boff[i >> 9];
        g_row[i] = r;
        g_cursor[i] = r;
    }
}

__global__ void k_fill(const int* __restrict__ src, const int* __restrict__ dst) {
    int i = blockIdx.x * blockDim.x + threadIdx.x;
    if (i < N_EDGES) {
        int pos = atomicAdd(&g_cursor[dst[i]], 1);
        g_srcs[pos] = src[i];
    }
}

// ---------------- fp32 GEMM: C[M,NC] = dinv[row] * (A[M,128] @ W[128,NC]) ----------------
template<int NC>
__global__ void __launch_bounds__(256, 2) k_gemm(const float* __restrict__ A,
                                                 const float* __restrict__ W,
                                                 float* __restrict__ C,
                                                 const float* __restrict__ dinv, int M) {
    constexpr int BM = 128, BK = 16;
    constexpr int TX = 16;            // threads along cols
    constexpr int CPT = NC / TX;      // cols per thread: 8 (NC=128) or 4 (NC=64)

    __shared__ float Xs[BK][BM + 4];  // transposed A tile
    __shared__ float Ws[BK][NC];

    const int tid  = threadIdx.x;
    const int tx   = tid % TX;
    const int ty   = tid / TX;        // 0..15, 8 rows each
    const int row0 = blockIdx.x * BM;

    float acc[8][CPT];
#pragma unroll
    for (int i = 0; i < 8; i++)
#pragma unroll
        for (int j = 0; j < CPT; j++) acc[i][j] = 0.f;

    for (int kc = 0; kc < 128; kc += BK) {
        // A tile: 128 rows x 16 k = 512 float4; 256 threads -> 2 each, transpose into Xs
#pragma unroll
        for (int l = 0; l < 2; l++) {
            int s = tid + l * 256;
            int r = s >> 2;          // row in tile
            int c = s & 3;           // float4 index along k
            float4 v = make_float4(0.f, 0.f, 0.f, 0.f);
            if (row0 + r < M)
                v = *(const float4*)(A + (size_t)(row0 + r) * 128 + kc + c * 4);
            Xs[c * 4 + 0][r] = v.x;
            Xs[c * 4 + 1][r] = v.y;
            Xs[c * 4 + 2][r] = v.z;
            Xs[c * 4 + 3][r] = v.w;
        }
        // W tile: BK x NC
#pragma unroll
        for (int l = 0; l < (BK * NC) / 1024; l++) {
            int s = tid + l * 256;
            int k = s / (NC / 4);
            int c = s % (NC / 4);
            *(float4*)&Ws[k][c * 4] = *(const float4*)(W + (size_t)(kc + k) * NC + c * 4);
        }
        __syncthreads();

#pragma unroll
        for (int k = 0; k < BK; k++) {
            float xr[8], wr[CPT];
            *(float4*)&xr[0] = *(const float4*)&Xs[k][ty * 8];
            *(float4*)&xr[4] = *(const float4*)&Xs[k][ty * 8 + 4];
#pragma unroll
            for (int j = 0; j < CPT / 4; j++)
                *(float4*)&wr[j * 4] = *(const float4*)&Ws[k][tx * CPT + j * 4];
#pragma unroll
            for (int i = 0; i < 8; i++)
#pragma unroll
                for (int j = 0; j < CPT; j++)
                    acc[i][j] += xr[i] * wr[j];
        }
        __syncthreads();
    }

#pragma unroll
    for (int i = 0; i < 8; i++) {
        int row = row0 + ty * 8 + i;
        if (row < M) {
            float sc = dinv[row];
            float* cp = C + (size_t)row * NC + tx * CPT;
#pragma unroll
            for (int j = 0; j < CPT / 4; j++) {
                float4 v = make_float4(acc[i][j * 4 + 0] * sc, acc[i][j * 4 + 1] * sc,
                                       acc[i][j * 4 + 2] * sc, acc[i][j * 4 + 3] * sc);
                *(float4*)(cp + j * 4) = v;
            }
        }
    }
}

// ---------------- layer-1 pull aggregation: warp per dst node, fused bias+relu ----------------
__global__ void __launch_bounds__(256) k_agg1(const float* __restrict__ b1) {
    int t = blockIdx.x * blockDim.x + threadIdx.x;
    int d = t >> 5;
    int lane = t & 31;
    if (d >= N_NODES) return;

    const float4* __restrict__ H = (const float4*)g_h1s;
    const int* __restrict__ S = g_srcs;
    int beg = g_row[d], end = g_row[d + 1];

    float4 acc = __ldg(&H[(size_t)d * 32 + lane]);       // self loop term (pre-scaled)
    int e = beg;
    for (; e + 4 <= end; e += 4) {
        int s0 = __ldg(&S[e]),     s1 = __ldg(&S[e + 1]);
        int s2 = __ldg(&S[e + 2]), s3 = __ldg(&S[e + 3]);
        float4 v0 = __ldg(&H[(size_t)s0 * 32 + lane]);
        float4 v1 = __ldg(&H[(size_t)s1 * 32 + lane]);
        float4 v2 = __ldg(&H[(size_t)s2 * 32 + lane]);
        float4 v3 = __ldg(&H[(size_t)s3 * 32 + lane]);
        acc.x += v0.x + v1.x + v2.x + v3.x;
        acc.y += v0.y + v1.y + v2.y + v3.y;
        acc.z += v0.z + v1.z + v2.z + v3.z;
        acc.w += v0.w + v1.w + v2.w + v3.w;
    }
    for (; e < end; e++) {
        int s = __ldg(&S[e]);
        float4 v = __ldg(&H[(size_t)s * 32 + lane]);
        acc.x += v.x; acc.y += v.y; acc.z += v.z; acc.w += v.w;
    }

    float di = g_dinv[d];
    float4 bb = __ldg(&((const float4*)b1)[lane]);
    acc.x = fmaxf(fmaf(acc.x, di, bb.x), 0.f);
    acc.y = fmaxf(fmaf(acc.y, di, bb.y), 0.f);
    acc.z = fmaxf(fmaf(acc.z, di, bb.z), 0.f);
    acc.w = fmaxf(fmaf(acc.w, di, bb.w), 0.f);
    ((float4*)g_agg1r)[(size_t)d * 32 + lane] = acc;
}

// ---------------- layer-2 pull aggregation: half-warp per dst node, fused bias ----------------
__global__ void __launch_bounds__(256) k_agg2(const float* __restrict__ b2,
                                              float* __restrict__ out) {
    int t = blockIdx.x * blockDim.x + threadIdx.x;
    int d = t >> 4;
    int lane = t & 15;
    if (d >= N_NODES) return;

    const float4* __restrict__ H = (const float4*)g_h2s;
    const int* __restrict__ S = g_srcs;
    int beg = g_row[d], end = g_row[d + 1];

    float4 acc = __ldg(&H[(size_t)d * 16 + lane]);       // self loop term
    int e = beg;
    for (; e + 4 <= end; e += 4) {
        int s0 = __ldg(&S[e]),     s1 = __ldg(&S[e + 1]);
        int s2 = __ldg(&S[e + 2]), s3 = __ldg(&S[e + 3]);
        float4 v0 = __ldg(&H[(size_t)s0 * 16 + lane]);
        float4 v1 = __ldg(&H[(size_t)s1 * 16 + lane]);
        float4 v2 = __ldg(&H[(size_t)s2 * 16 + lane]);
        float4 v3 = __ldg(&H[(size_t)s3 * 16 + lane]);
        acc.x += v0.x + v1.x + v2.x + v3.x;
        acc.y += v0.y + v1.y + v2.y + v3.y;
        acc.z += v0.z + v1.z + v2.z + v3.z;
        acc.w += v0.w + v1.w + v2.w + v3.w;
    }
    for (; e < end; e++) {
        int s = __ldg(&S[e]);
        float4 v = __ldg(&H[(size_t)s * 16 + lane]);
        acc.x += v.x; acc.y += v.y; acc.z += v.z; acc.w += v.w;
    }

    float di = g_dinv[d];
    float4 bb = __ldg(&((const float4*)b2)[lane]);
    acc.x = fmaf(acc.x, di, bb.x);
    acc.y = fmaf(acc.y, di, bb.y);
    acc.z = fmaf(acc.z, di, bb.z);
    acc.w = fmaf(acc.w, di, bb.w);
    ((float4*)out)[(size_t)d * 16 + lane] = acc;
}

// ---------------- launch ----------------
extern "C" void kernel_launch(void* const* d_in, const int* in_sizes, int n_in,
                              void* d_out, int out_size) {
    const float* x  = (const float*)d_in[0];
    const int*   ei = (const int*)  d_in[1];
    const float* W1 = (const float*)d_in[2];
    const float* b1 = (const float*)d_in[3];
    const float* W2 = (const float*)d_in[4];
    const float* b2 = (const float*)d_in[5];
    const int* src = ei;
    const int* dst = ei + N_EDGES;
    float* out = (float*)d_out;

    float *h1sp, *agg1rp, *h2sp, *dinvp;
    cudaGetSymbolAddress((void**)&h1sp,   g_h1s);
    cudaGetSymbolAddress((void**)&agg1rp, g_agg1r);
    cudaGetSymbolAddress((void**)&h2sp,   g_h2s);
    cudaGetSymbolAddress((void**)&dinvp,  g_dinv);

    const int NB_N = (N_NODES + 255) / 256;
    const int NB_E = (N_EDGES + 255) / 256;

    // CSR build (counting sort by dst) + dinv
    k_zero_cnt<<<NB_N, 256>>>();
    k_hist<<<NB_E, 256>>>(dst);
    k_scan1<<<N_SCAN_BLKS, SCAN_B>>>();
    k_scan2<<<1, 256>>>();
    k_scan3<<<NB_N, 256>>>();
    k_fill<<<NB_E, 256>>>(src, dst);

    // layer 1: GEMM (pre-scaled by dinv) -> pull aggregate (+bias, relu)
    k_gemm<HID_C><<<(N_NODES + 127) / 128, 256>>>(x, W1, h1sp, dinvp, N_NODES);
    k_agg1<<<(N_NODES * 32 + 255) / 256, 256>>>(b1);

    // layer 2
    k_gemm<OUT_C><<<(N_NODES + 127) / 128, 256>>>(agg1rp, W2, h2sp, dinvp, N_NODES);
    k_agg2<<<(N_NODES * 16 + 255) / 256, 256>>>(b2, out);
}

// round 7
// speedup vs baseline: 2.3852x; 1.1848x over previous
#include <cuda_runtime.h>
#include <cuda_fp16.h>
#include <cstddef>

#define N_NODES 100000
#define N_EDGES 1600000
#define IN_C  128
#define HID_C 128
#define OUT_C 64

#define SCAN_B 512
#define N_SCAN_BLKS ((N_NODES + SCAN_B - 1) / SCAN_B)   // 196

// ---------------- scratch (module-static; no allocations) ----------------
__device__ int    g_cnt   [N_NODES];
__device__ int    g_row   [N_NODES + 1];
__device__ int    g_cursor[N_NODES];
__device__ int    g_bsum  [N_SCAN_BLKS];
__device__ int    g_boff  [N_SCAN_BLKS];
__device__ int    g_srcs  [N_EDGES];                     // src ids sorted by dst
__device__ float  g_dinv  [N_NODES];
__device__ __half g_h1s   [(size_t)N_NODES * HID_C];     // fp16: dinv[n] * (x @ W1)[n]
__device__ float  g_agg1r [(size_t)N_NODES * HID_C];     // relu'd layer-1 output (fp32)
__device__ __half g_h2s   [(size_t)N_NODES * OUT_C];     // fp16: dinv[n] * (agg1r @ W2)[n]

// ---------------- CSR build ----------------
__global__ void k_zero_cnt() {
    int i = blockIdx.x * blockDim.x + threadIdx.x;
    if (i < N_NODES) g_cnt[i] = 0;
}

__global__ void k_hist(const int* __restrict__ dst) {
    int i = blockIdx.x * blockDim.x + threadIdx.x;
    if (i < N_EDGES) atomicAdd(&g_cnt[dst[i]], 1);
}

// per-block inclusive scan of 512 counts; also computes dinv = rsqrt(cnt+1)
__global__ void k_scan1() {
    __shared__ int sh[SCAN_B];
    int i = blockIdx.x * SCAN_B + threadIdx.x;
    int v = (i < N_NODES) ? g_cnt[i] : 0;
    if (i < N_NODES) g_dinv[i] = rsqrtf((float)(v + 1));   // +1 self loop
    sh[threadIdx.x] = v;
    __syncthreads();
#pragma unroll
    for (int off = 1; off < SCAN_B; off <<= 1) {
        int t = (threadIdx.x >= off) ? sh[threadIdx.x - off] : 0;
        __syncthreads();
        sh[threadIdx.x] += t;
        __syncthreads();
    }
    if (i < N_NODES) g_row[i] = sh[threadIdx.x] - v;       // exclusive within block
    if (threadIdx.x == SCAN_B - 1) g_bsum[blockIdx.x] = sh[SCAN_B - 1];
}

// scan of block sums (single block)
__global__ void k_scan2() {
    __shared__ int sh[256];
    int v = (threadIdx.x < N_SCAN_BLKS) ? g_bsum[threadIdx.x] : 0;
    sh[threadIdx.x] = v;
    __syncthreads();
#pragma unroll
    for (int off = 1; off < 256; off <<= 1) {
        int t = (threadIdx.x >= off) ? sh[threadIdx.x - off] : 0;
        __syncthreads();
        sh[threadIdx.x] += t;
        __syncthreads();
    }
    if (threadIdx.x < N_SCAN_BLKS) g_boff[threadIdx.x] = sh[threadIdx.x] - v;
    if (threadIdx.x == 0) g_row[N_NODES] = N_EDGES;
}

__global__ void k_scan3() {
    int i = blockIdx.x * blockDim.x + threadIdx.x;
    if (i < N_NODES) {
        int r = g_row[i] + g_boff[i >> 9];
        g_row[i] = r;
        g_cursor[i] = r;
    }
}

__global__ void k_fill(const int* __restrict__ src, const int* __restrict__ dst) {
    int i = blockIdx.x * blockDim.x + threadIdx.x;
    if (i < N_EDGES) {
        int pos = atomicAdd(&g_cursor[dst[i]], 1);
        g_srcs[pos] = src[i];
    }
}

// ---------------- fp32 GEMM: C[M,NC] = half( dinv[row] * (A[M,128] @ W[128,NC]) ) ----------------
template<int NC>
__global__ void __launch_bounds__(256, 2) k_gemm(const float* __restrict__ A,
                                                 const float* __restrict__ W,
                                                 __half* __restrict__ C,
                                                 const float* __restrict__ dinv, int M) {
    constexpr int BM = 128, BK = 16;
    constexpr int TX = 16;            // threads along cols
    constexpr int CPT = NC / TX;      // cols per thread: 8 (NC=128) or 4 (NC=64)

    __shared__ float Xs[BK][BM + 4];  // transposed A tile
    __shared__ float Ws[BK][NC];

    const int tid  = threadIdx.x;
    const int tx   = tid % TX;
    const int ty   = tid / TX;        // 0..15, 8 rows each
    const int row0 = blockIdx.x * BM;

    float acc[8][CPT];
#pragma unroll
    for (int i = 0; i < 8; i++)
#pragma unroll
        for (int j = 0; j < CPT; j++) acc[i][j] = 0.f;

    for (int kc = 0; kc < 128; kc += BK) {
        // A tile: 128 rows x 16 k = 512 float4; 256 threads -> 2 each, transpose into Xs
#pragma unroll
        for (int l = 0; l < 2; l++) {
            int s = tid + l * 256;
            int r = s >> 2;          // row in tile
            int c = s & 3;           // float4 index along k
            float4 v = make_float4(0.f, 0.f, 0.f, 0.f);
            if (row0 + r < M)
                v = *(const float4*)(A + (size_t)(row0 + r) * 128 + kc + c * 4);
            Xs[c * 4 + 0][r] = v.x;
            Xs[c * 4 + 1][r] = v.y;
            Xs[c * 4 + 2][r] = v.z;
            Xs[c * 4 + 3][r] = v.w;
        }
        // W tile: BK x NC
#pragma unroll
        for (int l = 0; l < (BK * NC) / 1024; l++) {
            int s = tid + l * 256;
            int k = s / (NC / 4);
            int c = s % (NC / 4);
            *(float4*)&Ws[k][c * 4] = *(const float4*)(W + (size_t)(kc + k) * NC + c * 4);
        }
        __syncthreads();

#pragma unroll
        for (int k = 0; k < BK; k++) {
            float xr[8], wr[CPT];
            *(float4*)&xr[0] = *(const float4*)&Xs[k][ty * 8];
            *(float4*)&xr[4] = *(const float4*)&Xs[k][ty * 8 + 4];
#pragma unroll
            for (int j = 0; j < CPT / 4; j++)
                *(float4*)&wr[j * 4] = *(const float4*)&Ws[k][tx * CPT + j * 4];
#pragma unroll
            for (int i = 0; i < 8; i++)
#pragma unroll
                for (int j = 0; j < CPT; j++)
                    acc[i][j] += xr[i] * wr[j];
        }
        __syncthreads();
    }

#pragma unroll
    for (int i = 0; i < 8; i++) {
        int row = row0 + ty * 8 + i;
        if (row < M) {
            float sc = dinv[row];
            __half2 hv[CPT / 2];
#pragma unroll
            for (int j = 0; j < CPT / 2; j++)
                hv[j] = __floats2half2_rn(acc[i][j * 2] * sc, acc[i][j * 2 + 1] * sc);
            // CPT=8 -> 16B store; CPT=4 -> 8B store. Both aligned.
            __half* cp = C + (size_t)row * NC + tx * CPT;
            if (CPT == 8) *(uint4*)cp = *(uint4*)hv;
            else          *(uint2*)cp = *(uint2*)hv;
        }
    }
}

// accumulate 8 fp16 channels (one uint4) into fp32 accumulator
__device__ __forceinline__ void acc8(float* a, uint4 u) {
    const __half2* h = (const __half2*)&u;
#pragma unroll
    for (int i = 0; i < 4; i++) {
        float2 f = __half22float2(h[i]);
        a[2 * i]     += f.x;
        a[2 * i + 1] += f.y;
    }
}

// ---------------- layer-1 pull aggregation: 16 lanes per dst node (8 ch each) ----------------
__global__ void __launch_bounds__(256) k_agg1(const float* __restrict__ b1) {
    int t = blockIdx.x * blockDim.x + threadIdx.x;
    int d = t >> 4;
    int lane = t & 15;           // channel group: 8 halves = 16B
    if (d >= N_NODES) return;

    const uint4* __restrict__ H = (const uint4*)g_h1s;   // 16 uint4 per row
    const int* __restrict__ S = g_srcs;
    int beg = g_row[d], end = g_row[d + 1];

    float a[8] = {0, 0, 0, 0, 0, 0, 0, 0};
    acc8(a, __ldg(&H[(size_t)d * 16 + lane]));           // self loop (pre-scaled)
    int e = beg;
    for (; e + 4 <= end; e += 4) {
        int s0 = __ldg(&S[e]),     s1 = __ldg(&S[e + 1]);
        int s2 = __ldg(&S[e + 2]), s3 = __ldg(&S[e + 3]);
        uint4 v0 = __ldg(&H[(size_t)s0 * 16 + lane]);
        uint4 v1 = __ldg(&H[(size_t)s1 * 16 + lane]);
        uint4 v2 = __ldg(&H[(size_t)s2 * 16 + lane]);
        uint4 v3 = __ldg(&H[(size_t)s3 * 16 + lane]);
        acc8(a, v0); acc8(a, v1); acc8(a, v2); acc8(a, v3);
    }
    for (; e < end; e++) {
        int s = __ldg(&S[e]);
        acc8(a, __ldg(&H[(size_t)s * 16 + lane]));
    }

    float di = g_dinv[d];
    float4 b0 = __ldg(&((const float4*)b1)[lane * 2]);
    float4 b4 = __ldg(&((const float4*)b1)[lane * 2 + 1]);
    float4 o0, o1;
    o0.x = fmaxf(fmaf(a[0], di, b0.x), 0.f);
    o0.y = fmaxf(fmaf(a[1], di, b0.y), 0.f);
    o0.z = fmaxf(fmaf(a[2], di, b0.z), 0.f);
    o0.w = fmaxf(fmaf(a[3], di, b0.w), 0.f);
    o1.x = fmaxf(fmaf(a[4], di, b4.x), 0.f);
    o1.y = fmaxf(fmaf(a[5], di, b4.y), 0.f);
    o1.z = fmaxf(fmaf(a[6], di, b4.z), 0.f);
    o1.w = fmaxf(fmaf(a[7], di, b4.w), 0.f);
    float4* op = (float4*)(g_agg1r + (size_t)d * HID_C + lane * 8);
    op[0] = o0;
    op[1] = o1;
}

// ---------------- layer-2 pull aggregation: 8 lanes per dst node (8 ch each) ----------------
__global__ void __launch_bounds__(256) k_agg2(const float* __restrict__ b2,
                                              float* __restrict__ out) {
    int t = blockIdx.x * blockDim.x + threadIdx.x;
    int d = t >> 3;
    int lane = t & 7;            // channel group: 8 halves = 16B
    if (d >= N_NODES) return;

    const uint4* __restrict__ H = (const uint4*)g_h2s;   // 8 uint4 per row
    const int* __restrict__ S = g_srcs;
    int beg = g_row[d], end = g_row[d + 1];

    float a[8] = {0, 0, 0, 0, 0, 0, 0, 0};
    acc8(a, __ldg(&H[(size_t)d * 8 + lane]));            // self loop
    int e = beg;
    for (; e + 4 <= end; e += 4) {
        int s0 = __ldg(&S[e]),     s1 = __ldg(&S[e + 1]);
        int s2 = __ldg(&S[e + 2]), s3 = __ldg(&S[e + 3]);
        uint4 v0 = __ldg(&H[(size_t)s0 * 8 + lane]);
        uint4 v1 = __ldg(&H[(size_t)s1 * 8 + lane]);
        uint4 v2 = __ldg(&H[(size_t)s2 * 8 + lane]);
        uint4 v3 = __ldg(&H[(size_t)s3 * 8 + lane]);
        acc8(a, v0); acc8(a, v1); acc8(a, v2); acc8(a, v3);
    }
    for (; e < end; e++) {
        int s = __ldg(&S[e]);
        acc8(a, __ldg(&H[(size_t)s * 8 + lane]));
    }

    float di = g_dinv[d];
    float4 b0 = __ldg(&((const float4*)b2)[lane * 2]);
    float4 b4 = __ldg(&((const float4*)b2)[lane * 2 + 1]);
    float4 o0, o1;
    o0.x = fmaf(a[0], di, b0.x);
    o0.y = fmaf(a[1], di, b0.y);
    o0.z = fmaf(a[2], di, b0.z);
    o0.w = fmaf(a[3], di, b0.w);
    o1.x = fmaf(a[4], di, b4.x);
    o1.y = fmaf(a[5], di, b4.y);
    o1.z = fmaf(a[6], di, b4.z);
    o1.w = fmaf(a[7], di, b4.w);
    float4* op = (float4*)(out + (size_t)d * OUT_C + lane * 8);
    op[0] = o0;
    op[1] = o1;
}

// ---------------- launch ----------------
extern "C" void kernel_launch(void* const* d_in, const int* in_sizes, int n_in,
                              void* d_out, int out_size) {
    const float* x  = (const float*)d_in[0];
    const int*   ei = (const int*)  d_in[1];
    const float* W1 = (const float*)d_in[2];
    const float* b1 = (const float*)d_in[3];
    const float* W2 = (const float*)d_in[4];
    const float* b2 = (const float*)d_in[5];
    const int* src = ei;
    const int* dst = ei + N_EDGES;
    float* out = (float*)d_out;

    __half *h1sp, *h2sp;
    float *agg1rp, *dinvp;
    cudaGetSymbolAddress((void**)&h1sp,   g_h1s);
    cudaGetSymbolAddress((void**)&agg1rp, g_agg1r);
    cudaGetSymbolAddress((void**)&h2sp,   g_h2s);
    cudaGetSymbolAddress((void**)&dinvp,  g_dinv);

    const int NB_N = (N_NODES + 255) / 256;
    const int NB_E = (N_EDGES + 255) / 256;

    // CSR build (counting sort by dst) + dinv
    k_zero_cnt<<<NB_N, 256>>>();
    k_hist<<<NB_E, 256>>>(dst);
    k_scan1<<<N_SCAN_BLKS, SCAN_B>>>();
    k_scan2<<<1, 256>>>();
    k_scan3<<<NB_N, 256>>>();
    k_fill<<<NB_E, 256>>>(src, dst);

    // layer 1: GEMM (pre-scaled by dinv, fp16 out) -> pull aggregate (+bias, relu)
    k_gemm<HID_C><<<(N_NODES + 127) / 128, 256>>>(x, W1, h1sp, dinvp, N_NODES);
    k_agg1<<<(N_NODES * 16 + 255) / 256, 256>>>(b1);

    // layer 2
    k_gemm<OUT_C><<<(N_NODES + 127) / 128, 256>>>(agg1rp, W2, h2sp, dinvp, N_NODES);
    k_agg2<<<(N_NODES * 8 + 255) / 256, 256>>>(b2, out);
}

// round 8
// speedup vs baseline: 3.0145x; 1.2638x over previous
#include <cuda_runtime.h>
#include <cuda_fp16.h>
#include <mma.h>
#include <cstddef>

#define N_NODES 100000
#define N_EDGES 1600000
#define IN_C  128
#define HID_C 128
#define OUT_C 64

#define SCAN_B 512
#define N_SCAN_BLKS ((N_NODES + SCAN_B - 1) / SCAN_B)   // 196

// ---------------- scratch (module-static; no allocations) ----------------
__device__ int    g_cnt   [N_NODES];
__device__ int    g_row   [N_NODES + 1];
__device__ int    g_cursor[N_NODES];
__device__ int    g_bsum  [N_SCAN_BLKS];
__device__ int    g_boff  [N_SCAN_BLKS];
__device__ int    g_srcs  [N_EDGES];                     // src ids sorted by dst
__device__ float  g_dinv  [N_NODES];
__device__ __half g_w1t   [(size_t)HID_C * IN_C];        // W1^T fp16: [n][k]
__device__ __half g_w2t   [(size_t)OUT_C * HID_C];       // W2^T fp16: [n][k]
__device__ __half g_h1s   [(size_t)N_NODES * HID_C];     // fp16: dinv[n] * (x @ W1)[n]
__device__ float  g_agg1r [(size_t)N_NODES * HID_C];     // relu'd layer-1 output (fp32)
__device__ __half g_h2s   [(size_t)N_NODES * OUT_C];     // fp16: dinv[n] * (agg1r @ W2)[n]

// ---------------- CSR build ----------------
__global__ void k_zero_cnt() {
    int i = blockIdx.x * blockDim.x + threadIdx.x;
    if (i < N_NODES) g_cnt[i] = 0;
}

__global__ void k_hist(const int* __restrict__ dst) {
    int i = blockIdx.x * blockDim.x + threadIdx.x;
    if (i < N_EDGES) atomicAdd(&g_cnt[dst[i]], 1);
}

// per-block inclusive scan of 512 counts; also computes dinv = rsqrt(cnt+1)
__global__ void k_scan1() {
    __shared__ int sh[SCAN_B];
    int i = blockIdx.x * SCAN_B + threadIdx.x;
    int v = (i < N_NODES) ? g_cnt[i] : 0;
    if (i < N_NODES) g_dinv[i] = rsqrtf((float)(v + 1));   // +1 self loop
    sh[threadIdx.x] = v;
    __syncthreads();
#pragma unroll
    for (int off = 1; off < SCAN_B; off <<= 1) {
        int t = (threadIdx.x >= off) ? sh[threadIdx.x - off] : 0;
        __syncthreads();
        sh[threadIdx.x] += t;
        __syncthreads();
    }
    if (i < N_NODES) g_row[i] = sh[threadIdx.x] - v;       // exclusive within block
    if (threadIdx.x == SCAN_B - 1) g_bsum[blockIdx.x] = sh[SCAN_B - 1];
}

// scan of block sums (single block)
__global__ void k_scan2() {
    __shared__ int sh[256];
    int v = (threadIdx.x < N_SCAN_BLKS) ? g_bsum[threadIdx.x] : 0;
    sh[threadIdx.x] = v;
    __syncthreads();
#pragma unroll
    for (int off = 1; off < 256; off <<= 1) {
        int t = (threadIdx.x >= off) ? sh[threadIdx.x - off] : 0;
        __syncthreads();
        sh[threadIdx.x] += t;
        __syncthreads();
    }
    if (threadIdx.x < N_SCAN_BLKS) g_boff[threadIdx.x] = sh[threadIdx.x] - v;
    if (threadIdx.x == 0) g_row[N_NODES] = N_EDGES;
}

__global__ void k_scan3() {
    int i = blockIdx.x * blockDim.x + threadIdx.x;
    if (i < N_NODES) {
        int r = g_row[i] + g_boff[i >> 9];
        g_row[i] = r;
        g_cursor[i] = r;
    }
}

__global__ void k_fill(const int* __restrict__ src, const int* __restrict__ dst) {
    int i = blockIdx.x * blockDim.x + threadIdx.x;
    if (i < N_EDGES) {
        int pos = atomicAdd(&g_cursor[dst[i]], 1);
        g_srcs[pos] = src[i];
    }
}

// ---------------- weight transpose + fp16 convert ----------------
__global__ void k_prep_w(const float* __restrict__ W1, const float* __restrict__ W2) {
    int i = blockIdx.x * blockDim.x + threadIdx.x;
    if (i < HID_C * IN_C) {                         // Wt1[n][k] = W1[k][n]
        int n = i / IN_C, k = i % IN_C;
        g_w1t[i] = __float2half_rn(W1[(size_t)k * HID_C + n]);
    } else if (i < HID_C * IN_C + OUT_C * HID_C) {  // Wt2[n][k] = W2[k][n]
        int j = i - HID_C * IN_C;
        int n = j / HID_C, k = j % HID_C;
        g_w2t[j] = __float2half_rn(W2[(size_t)k * OUT_C + n]);
    }
}

// ---------------- tensor-core GEMM: C[M,NC] = half( (diag(dinv)·A[M,128]) @ Wt^T ) ----------------
// A fp32 row-major (stride 128), Wt fp16 [NC][128], C fp16 row-major (stride NC).
template<int NC>
__global__ void __launch_bounds__(256) k_gemm_mma(const float* __restrict__ A,
                                                  const __half* __restrict__ Wt,
                                                  __half* __restrict__ C,
                                                  const float* __restrict__ dinv, int M) {
    using namespace nvcuda;
    constexpr int KC = 64, ST = KC + 16;   // smem stride (halves), 32B-aligned rows
    constexpr int NFR = NC / 32;           // n-frags per warp: 128->4, 64->2

    __shared__ __half As[128 * ST];
    __shared__ __half Bs[NC * ST];

    const int tid    = threadIdx.x;
    const int wid    = tid >> 5;
    const int lane   = tid & 31;
    const int warp_m = wid & 3;            // 4 warp-rows x 32 rows
    const int warp_n = wid >> 2;           // 2 warp-cols x NC/2 cols
    const int row_blk = blockIdx.x * 128;

    wmma::fragment<wmma::accumulator, 16, 16, 16, float> cf[2][NFR];
#pragma unroll
    for (int i = 0; i < 2; i++)
#pragma unroll
        for (int j = 0; j < NFR; j++) wmma::fill_fragment(cf[i][j], 0.f);

    for (int kc = 0; kc < 128; kc += KC) {
        // A chunk: 128 rows x 64 floats, scaled by dinv, converted to fp16. 2 thr/row.
        {
            int r = tid >> 1;
            int hh = tid & 1;
            int grow = row_blk + r;
            float sc = (grow < M) ? dinv[grow] : 0.f;
            const float4* gp = (const float4*)(A + (size_t)grow * 128 + kc + hh * 32);
            __half* sp = As + r * ST + hh * 32;
#pragma unroll
            for (int j = 0; j < 8; j++) {
                float4 v = (grow < M) ? __ldg(&gp[j]) : make_float4(0.f, 0.f, 0.f, 0.f);
                __half2 h0 = __floats2half2_rn(v.x * sc, v.y * sc);
                __half2 h1 = __floats2half2_rn(v.z * sc, v.w * sc);
                ((__half2*)(sp + j * 4))[0] = h0;
                ((__half2*)(sp + j * 4))[1] = h1;
            }
        }
        // B chunk: NC rows x 64 halves (uint4 copies)
        {
#pragma unroll
            for (int i = 0; i < (NC * 8) / 256; i++) {
                int u = tid + i * 256;
                int n = u >> 3, k8 = u & 7;
                uint4 v = *(const uint4*)(Wt + (size_t)n * 128 + kc + k8 * 8);
                *(uint4*)(Bs + n * ST + k8 * 8) = v;
            }
        }
        __syncthreads();

#pragma unroll
        for (int kf = 0; kf < KC / 16; kf++) {
            wmma::fragment<wmma::matrix_a, 16, 16, 16, __half, wmma::row_major> af[2];
            wmma::load_matrix_sync(af[0], As + (warp_m * 32 +  0) * ST + kf * 16, ST);
            wmma::load_matrix_sync(af[1], As + (warp_m * 32 + 16) * ST + kf * 16, ST);
#pragma unroll
            for (int nf = 0; nf < NFR; nf++) {
                wmma::fragment<wmma::matrix_b, 16, 16, 16, __half, wmma::col_major> bf;
                wmma::load_matrix_sync(bf, Bs + (warp_n * (NC / 2) + nf * 16) * ST + kf * 16, ST);
                wmma::mma_sync(cf[0][nf], af[0], bf, cf[0][nf]);
                wmma::mma_sync(cf[1][nf], af[1], bf, cf[1][nf]);
            }
        }
        __syncthreads();   // also protects As before staging reuse below
    }

    // epilogue: stage fp32 frag -> convert fp16 -> gmem (per-warp disjoint staging in As)
    float* stage = (float*)As + wid * 256;
#pragma unroll
    for (int mf = 0; mf < 2; mf++) {
        int row0 = row_blk + warp_m * 32 + mf * 16;
        if (row0 + 16 > M) continue;          // M is a multiple of 16
#pragma unroll
        for (int nf = 0; nf < NFR; nf++) {
            wmma::store_matrix_sync(stage, cf[mf][nf], 16, wmma::mem_row_major);
            __syncwarp();
            int r = lane >> 1, c = (lane & 1) * 8;
            const float* sp = stage + r * 16 + c;
            __half hv[8];
#pragma unroll
            for (int j = 0; j < 8; j++) hv[j] = __float2half_rn(sp[j]);
            int col0 = warp_n * (NC / 2) + nf * 16 + c;
            *(uint4*)(C + (size_t)(row0 + r) * NC + col0) = *(uint4*)hv;
            __syncwarp();
        }
    }
}

// accumulate 8 fp16 channels (one uint4) into fp32 accumulator
__device__ __forceinline__ void acc8(float* a, uint4 u) {
    const __half2* h = (const __half2*)&u;
#pragma unroll
    for (int i = 0; i < 4; i++) {
        float2 f = __half22float2(h[i]);
        a[2 * i]     += f.x;
        a[2 * i + 1] += f.y;
    }
}

// ---------------- layer-1 pull aggregation: 16 lanes per dst node (8 ch each) ----------------
__global__ void __launch_bounds__(256) k_agg1(const float* __restrict__ b1) {
    int t = blockIdx.x * blockDim.x + threadIdx.x;
    int d = t >> 4;
    int lane = t & 15;           // channel group: 8 halves = 16B
    if (d >= N_NODES) return;

    const uint4* __restrict__ H = (const uint4*)g_h1s;   // 16 uint4 per row
    const int* __restrict__ S = g_srcs;
    int beg = g_row[d], end = g_row[d + 1];

    float a[8] = {0, 0, 0, 0, 0, 0, 0, 0};
    acc8(a, __ldg(&H[(size_t)d * 16 + lane]));           // self loop (pre-scaled)
    int e = beg;
    for (; e + 4 <= end; e += 4) {
        int s0 = __ldg(&S[e]),     s1 = __ldg(&S[e + 1]);
        int s2 = __ldg(&S[e + 2]), s3 = __ldg(&S[e + 3]);
        uint4 v0 = __ldg(&H[(size_t)s0 * 16 + lane]);
        uint4 v1 = __ldg(&H[(size_t)s1 * 16 + lane]);
        uint4 v2 = __ldg(&H[(size_t)s2 * 16 + lane]);
        uint4 v3 = __ldg(&H[(size_t)s3 * 16 + lane]);
        acc8(a, v0); acc8(a, v1); acc8(a, v2); acc8(a, v3);
    }
    for (; e < end; e++) {
        int s = __ldg(&S[e]);
        acc8(a, __ldg(&H[(size_t)s * 16 + lane]));
    }

    float di = g_dinv[d];
    float4 b0 = __ldg(&((const float4*)b1)[lane * 2]);
    float4 b4 = __ldg(&((const float4*)b1)[lane * 2 + 1]);
    float4 o0, o1;
    o0.x = fmaxf(fmaf(a[0], di, b0.x), 0.f);
    o0.y = fmaxf(fmaf(a[1], di, b0.y), 0.f);
    o0.z = fmaxf(fmaf(a[2], di, b0.z), 0.f);
    o0.w = fmaxf(fmaf(a[3], di, b0.w), 0.f);
    o1.x = fmaxf(fmaf(a[4], di, b4.x), 0.f);
    o1.y = fmaxf(fmaf(a[5], di, b4.y), 0.f);
    o1.z = fmaxf(fmaf(a[6], di, b4.z), 0.f);
    o1.w = fmaxf(fmaf(a[7], di, b4.w), 0.f);
    float4* op = (float4*)(g_agg1r + (size_t)d * HID_C + lane * 8);
    op[0] = o0;
    op[1] = o1;
}

// ---------------- layer-2 pull aggregation: 8 lanes per dst node (8 ch each) ----------------
__global__ void __launch_bounds__(256) k_agg2(const float* __restrict__ b2,
                                              float* __restrict__ out) {
    int t = blockIdx.x * blockDim.x + threadIdx.x;
    int d = t >> 3;
    int lane = t & 7;            // channel group: 8 halves = 16B
    if (d >= N_NODES) return;

    const uint4* __restrict__ H = (const uint4*)g_h2s;   // 8 uint4 per row
    const int* __restrict__ S = g_srcs;
    int beg = g_row[d], end = g_row[d + 1];

    float a[8] = {0, 0, 0, 0, 0, 0, 0, 0};
    acc8(a, __ldg(&H[(size_t)d * 8 + lane]));            // self loop
    int e = beg;
    for (; e + 4 <= end; e += 4) {
        int s0 = __ldg(&S[e]),     s1 = __ldg(&S[e + 1]);
        int s2 = __ldg(&S[e + 2]), s3 = __ldg(&S[e + 3]);
        uint4 v0 = __ldg(&H[(size_t)s0 * 8 + lane]);
        uint4 v1 = __ldg(&H[(size_t)s1 * 8 + lane]);
        uint4 v2 = __ldg(&H[(size_t)s2 * 8 + lane]);
        uint4 v3 = __ldg(&H[(size_t)s3 * 8 + lane]);
        acc8(a, v0); acc8(a, v1); acc8(a, v2); acc8(a, v3);
    }
    for (; e < end; e++) {
        int s = __ldg(&S[e]);
        acc8(a, __ldg(&H[(size_t)s * 8 + lane]));
    }

    float di = g_dinv[d];
    float4 b0 = __ldg(&((const float4*)b2)[lane * 2]);
    float4 b4 = __ldg(&((const float4*)b2)[lane * 2 + 1]);
    float4 o0, o1;
    o0.x = fmaf(a[0], di, b0.x);
    o0.y = fmaf(a[1], di, b0.y);
    o0.z = fmaf(a[2], di, b0.z);
    o0.w = fmaf(a[3], di, b0.w);
    o1.x = fmaf(a[4], di, b4.x);
    o1.y = fmaf(a[5], di, b4.y);
    o1.z = fmaf(a[6], di, b4.z);
    o1.w = fmaf(a[7], di, b4.w);
    float4* op = (float4*)(out + (size_t)d * OUT_C + lane * 8);
    op[0] = o0;
    op[1] = o1;
}

// ---------------- launch ----------------
extern "C" void kernel_launch(void* const* d_in, const int* in_sizes, int n_in,
                              void* d_out, int out_size) {
    const float* x  = (const float*)d_in[0];
    const int*   ei = (const int*)  d_in[1];
    const float* W1 = (const float*)d_in[2];
    const float* b1 = (const float*)d_in[3];
    const float* W2 = (const float*)d_in[4];
    const float* b2 = (const float*)d_in[5];
    const int* src = ei;
    const int* dst = ei + N_EDGES;
    float* out = (float*)d_out;

    __half *h1sp, *h2sp, *w1tp, *w2tp;
    float *agg1rp, *dinvp;
    cudaGetSymbolAddress((void**)&h1sp,   g_h1s);
    cudaGetSymbolAddress((void**)&agg1rp, g_agg1r);
    cudaGetSymbolAddress((void**)&h2sp,   g_h2s);
    cudaGetSymbolAddress((void**)&dinvp,  g_dinv);
    cudaGetSymbolAddress((void**)&w1tp,   g_w1t);
    cudaGetSymbolAddress((void**)&w2tp,   g_w2t);

    const int NB_N = (N_NODES + 255) / 256;
    const int NB_E = (N_EDGES + 255) / 256;

    // CSR build (counting sort by dst) + dinv; weight prep
    k_zero_cnt<<<NB_N, 256>>>();
    k_hist<<<NB_E, 256>>>(dst);
    k_prep_w<<<(HID_C * IN_C + OUT_C * HID_C + 255) / 256, 256>>>(W1, W2);
    k_scan1<<<N_SCAN_BLKS, SCAN_B>>>();
    k_scan2<<<1, 256>>>();
    k_scan3<<<NB_N, 256>>>();
    k_fill<<<NB_E, 256>>>(src, dst);

    // layer 1: tensor GEMM (dinv folded into A, fp16 out) -> pull aggregate (+bias, relu)
    k_gemm_mma<HID_C><<<(N_NODES + 127) / 128, 256>>>(x, w1tp, h1sp, dinvp, N_NODES);
    k_agg1<<<(N_NODES * 16 + 255) / 256, 256>>>(b1);

    // layer 2
    k_gemm_mma<OUT_C><<<(N_NODES + 127) / 128, 256>>>(agg1rp, w2tp, h2sp, dinvp, N_NODES);
    k_agg2<<<(N_NODES * 8 + 255) / 256, 256>>>(b2, out);
}